// round 16
// baseline (speedup 1.0000x reference)
#include <cuda_runtime.h>
#include <cuda_fp16.h>
#include <math.h>

#define Bsz   4
#define Lsz   4096
#define Esz   1024
#define HEADS 64
#define SPLIT 8
#define CHUNK 512
#define KC    32
#define NG    (CHUNK / KC)
#define DEPTH 4

#define PART   8320
#define OFF_W  8192

typedef unsigned int u32;

__device__ float g_part[HEADS * SPLIT * PART];
__device__ __half g_kvt_h[HEADS * 8192];   // KV^T fp16 [head][m][f]
__device__ float g_w[HEADS * 128];
__device__ int   g_cnt[HEADS];             // zero-init; self-resetting

// ---- helpers ---------------------------------------------------------------
__device__ __forceinline__ void mma_f16(float* c, const u32* a, u32 b0, u32 b1) {
    asm("mma.sync.aligned.m16n8k16.row.col.f32.f16.f16.f32 "
        "{%0,%1,%2,%3}, {%4,%5,%6,%7}, {%8,%9}, {%0,%1,%2,%3};"
        : "+f"(c[0]), "+f"(c[1]), "+f"(c[2]), "+f"(c[3])
        : "r"(a[0]), "r"(a[1]), "r"(a[2]), "r"(a[3]), "r"(b0), "r"(b1));
}
__device__ __forceinline__ u32 sh_addr(const void* p) {
    return (u32)__cvta_generic_to_shared(p);
}
__device__ __forceinline__ void ldsm4(u32* r, u32 a) {
    asm volatile("ldmatrix.sync.aligned.m8n8.x4.shared.b16 {%0,%1,%2,%3}, [%4];"
        : "=r"(r[0]), "=r"(r[1]), "=r"(r[2]), "=r"(r[3]) : "r"(a));
}
__device__ __forceinline__ void ldsm4t(u32* r, u32 a) {
    asm volatile("ldmatrix.sync.aligned.m8n8.x4.trans.shared.b16 {%0,%1,%2,%3}, [%4];"
        : "=r"(r[0]), "=r"(r[1]), "=r"(r[2]), "=r"(r[3]) : "r"(a));
}
__device__ __forceinline__ u32 pk16(float a, float b) {
    u32 r;
    asm("cvt.rn.f16x2.f32 %0, %1, %2;" : "=r"(r) : "f"(b), "f"(a));
    return r;
}
__device__ __forceinline__ void cpa16(u32 saddr, const void* g) {
    asm volatile("cp.async.ca.shared.global [%0], [%1], 16;" :: "r"(saddr), "l"(g));
}
__device__ __forceinline__ float4 ldcs4(const float* p) {
    float4 r;
    asm volatile("ld.global.cs.v4.f32 {%0,%1,%2,%3}, [%4];"
        : "=f"(r.x), "=f"(r.y), "=f"(r.z), "=f"(r.w) : "l"(p));
    return r;
}
__device__ __forceinline__ void stcs2(float* p, float a, float b) {
    asm volatile("st.global.cs.v2.f32 [%0], {%1,%2};" :: "l"(p), "f"(a), "f"(b));
}
#define BARS(id) asm volatile("bar.sync %0, 256;"   :: "r"(id) : "memory")
#define BARA(id) asm volatile("bar.arrive %0, 256;" :: "r"(id) : "memory")

// ---------------------------------------------------------------------------
// Phase 1: warp-specialized (4 producer + 4 consumer warps), 4-deep ring,
// single-plane fp16 V. Last-arriving block per head performs the 8-way
// reduction from L2-hot partials and emits fp16 KV^T + fp32 w.
// ---------------------------------------------------------------------------
#define XSTR 136
#define TSTR 72
#define ST_X (KC * XSTR)
#define ST_T (KC * TSTR)
#define SM1_BYTES ((DEPTH*ST_X + DEPTH*ST_T) * 2 + (CHUNK*3 + 1024) * 4)

__global__ __launch_bounds__(256, 2) void k_phase1(const float* __restrict__ K,
                                                   const float* __restrict__ V,
                                                   const float* __restrict__ M) {
    extern __shared__ char sm1[];
    __half* Xh = (__half*)sm1;
    __half* Th = Xh + DEPTH * ST_X;
    float* ssh = (float*)(Th + DEPTH * ST_T);
    float* csh = ssh + CHUNK;
    float* msh = csh + CHUNK;
    float* ksp = msh + CHUNK;

    __shared__ int amLast;

    int blk = blockIdx.x;
    int n  = blk >> 3;
    int sp = blk & 7;
    int b = n >> 4, h = n & 15;
    int l0 = sp * CHUNK;

    const float* kb = K + ((size_t)b * Lsz + l0) * Esz + h * 64;
    const float* vb = V + ((size_t)b * Lsz + l0) * Esz + h * 64;
    const float* mb = M + (size_t)b * Lsz + l0;

    int t = threadIdx.x;
    for (int i = t; i < CHUNK; i += 256) {
        int l = l0 + i;
        float ang = 1.5707963267948966f * (float)(l + 1) / (float)Lsz;
        float m = mb[i];
        ssh[i] = sinf(ang) * m;
        csh[i] = cosf(ang) * m;
        msh[i] = m;
    }
    __syncthreads();

    float* p = g_part + (size_t)blk * PART;

    if (t < 128) {
        // ------------------ producer warps ------------------
        int ddg = (t & 15) * 4;
        int pr  = t >> 4;
        float ksr[4] = {0,0,0,0}, kcr[4] = {0,0,0,0};

        for (int g = 0; g < NG; ++g) {
            int bb = g & (DEPTH - 1);
            if (g >= DEPTH) BARS(5 + bb);
            __half* xh = Xh + bb * ST_X;
            __half* th = Th + bb * ST_T;
            #pragma unroll
            for (int jj = 0; jj < 4; ++jj) {
                int tok = jj * 8 + pr;
                int li = g * KC + tok;
                float4 k4 = ldcs4(&kb[(size_t)li * Esz + ddg]);
                float4 v4 = ldcs4(&vb[(size_t)li * Esz + ddg]);
                float s = ssh[li], c = csh[li], m = msh[li];
                float rk[4] = { fmaxf(k4.x, 0.f), fmaxf(k4.y, 0.f),
                                fmaxf(k4.z, 0.f), fmaxf(k4.w, 0.f) };
                float sk[4], ck[4], vm[4] = { v4.x*m, v4.y*m, v4.z*m, v4.w*m };
                #pragma unroll
                for (int i = 0; i < 4; ++i) {
                    sk[i] = rk[i] * s; ck[i] = rk[i] * c;
                    ksr[i] += sk[i];   kcr[i] += ck[i];
                }
                *(uint2*)&xh[tok * XSTR + ddg] =
                    make_uint2(pk16(sk[0], sk[1]), pk16(sk[2], sk[3]));
                *(uint2*)&xh[tok * XSTR + 64 + ddg] =
                    make_uint2(pk16(ck[0], ck[1]), pk16(ck[2], ck[3]));
                *(uint2*)&th[tok * TSTR + ddg] =
                    make_uint2(pk16(vm[0], vm[1]), pk16(vm[2], vm[3]));
            }
            __threadfence_block();
            BARA(1 + bb);
        }
        #pragma unroll
        for (int i = 0; i < 4; ++i) {
            ksp[pr * 128 + ddg + i]      = ksr[i];
            ksp[pr * 128 + 64 + ddg + i] = kcr[i];
        }
    } else {
        // ------------------ consumer warps ------------------
        int t2 = t - 128;
        int w = t2 >> 5, lane = t2 & 31;
        int gid = lane >> 2, tid = lane & 3;
        int rb = w * 32;
        int ra = (lane & 7) + ((lane >> 4) & 1) * 8;
        int ca = ((lane >> 3) & 1) * 8;

        float acc[2][8][4];
        #pragma unroll
        for (int i = 0; i < 2; ++i)
            #pragma unroll
            for (int j = 0; j < 8; ++j)
                #pragma unroll
                for (int q = 0; q < 4; ++q) acc[i][j][q] = 0.f;

        for (int g = 0; g < NG; ++g) {
            int bb = g & (DEPTH - 1);
            BARS(1 + bb);
            __half* xh = Xh + bb * ST_X;
            __half* th = Th + bb * ST_T;
            #pragma unroll
            for (int ko = 0; ko < KC; ko += 16) {
                u32 ah[2][4];
                #pragma unroll
                for (int i = 0; i < 2; ++i)
                    ldsm4t(ah[i], sh_addr(&xh[(ko + ra) * XSTR + rb + i * 16 + ca]));
                #pragma unroll
                for (int jp = 0; jp < 4; ++jp) {
                    u32 bh[4];
                    ldsm4t(bh, sh_addr(&th[(ko + ra) * TSTR + jp * 16 + ca]));
                    #pragma unroll
                    for (int i = 0; i < 2; ++i) {
                        mma_f16(acc[i][2 * jp],     ah[i], bh[0], bh[2]);
                        mma_f16(acc[i][2 * jp + 1], ah[i], bh[1], bh[3]);
                    }
                }
            }
            BARA(5 + bb);
        }
        #pragma unroll
        for (int i = 0; i < 2; ++i) {
            int r = rb + 16 * i + gid;
            #pragma unroll
            for (int j = 0; j < 8; ++j) {
                int nb = j * 8 + tid * 2;
                *(float2*)&p[r * 64 + nb]       = make_float2(acc[i][j][0], acc[i][j][1]);
                *(float2*)&p[(r + 8) * 64 + nb] = make_float2(acc[i][j][2], acc[i][j][3]);
            }
        }
    }
    __syncthreads();
    if (t < 128) {
        float s = 0.f;
        #pragma unroll
        for (int r = 0; r < 8; ++r) s += ksp[r * 128 + t];
        p[OFF_W + t] = s;
    }
    __syncthreads();

    // ---- fused cross-split reduction: last-arriving block of this head ----
    if (t == 0) {
        __threadfence();                       // publish this block's partials
        int old = atomicAdd(&g_cnt[n], 1);
        amLast = (old == SPLIT - 1) ? 1 : 0;
    }
    __syncthreads();
    if (amLast) {
        if (t == 0) g_cnt[n] = 0;              // reset for next graph replay
        __threadfence();                       // acquire others' partials
        const float* pb = g_part + (size_t)(n * SPLIT) * PART;
        for (int idx = t; idx < 8192; idx += 256) {
            int f = idx >> 6, m = idx & 63;
            float s = 0.f;
            #pragma unroll
            for (int sp2 = 0; sp2 < SPLIT; ++sp2)
                s += pb[(size_t)sp2 * PART + idx];
            g_kvt_h[(size_t)n * 8192 + m * 128 + f] = __float2half_rn(s);
        }
        if (t < 128) {
            float s = 0.f;
            #pragma unroll
            for (int sp2 = 0; sp2 < SPLIT; ++sp2)
                s += pb[(size_t)sp2 * PART + OFF_W + t];
            g_w[n * 128 + t] = s;
        }
    }
}

// ---------------------------------------------------------------------------
// Phase 2 (R15, proven ~43us): 128-token blocks = 2 substages of 64 tokens,
// double-buffered X; Q(st+1) prefetched into regs before MMA(st); KV via
// cp.async. 8 warps as 2(tok)x4(m). 3 blocks/SM. Streaming Q loads/O stores.
// ---------------------------------------------------------------------------
#define TT2  128
#define SB2  64
#define NSUB 2
#define FS2  136
#define XB2  (SB2 * FS2)
#define X2_OFF   0
#define KH_OFF   (2 * XB2 * 2)
#define FP_OFF   (KH_OFF + 64 * FS2 * 2)
#define SM2_BYTES (FP_OFF + (128 + TT2 * 3) * 4)

__global__ __launch_bounds__(256, 3) void k_phase2(const float* __restrict__ Q,
                                                   float* __restrict__ O) {
    extern __shared__ char sm2[];
    __half* X   = (__half*)(sm2 + X2_OFF);
    __half* Kh  = (__half*)(sm2 + KH_OFF);
    float* wsh = (float*)(sm2 + FP_OFF);
    float* zsh = wsh + 128;
    float* ssh = zsh + TT2;
    float* csh = ssh + TT2;

    int blk = blockIdx.x;
    int n = blk >> 5;
    int tile = blk & 31;
    int b = n >> 4, h = n & 15;
    int l0 = tile * TT2;

    const float* qb = Q + ((size_t)b * Lsz + l0) * Esz + h * 64;
    int t = threadIdx.x;

    for (int idx = t; idx < 1024; idx += 256) {
        int mr = idx >> 4, c = idx & 15;
        cpa16(sh_addr(&Kh[mr * FS2 + c * 8]),
              &g_kvt_h[(size_t)n * 8192 + mr * 128 + c * 8]);
    }
    asm volatile("cp.async.commit_group;" ::: "memory");

    if (t < 128) {
        wsh[t] = g_w[n * 128 + t];
        int l = l0 + t;
        float ang = 1.5707963267948966f * (float)(l + 1) / (float)Lsz;
        ssh[t] = sinf(ang);
        csh[t] = cosf(ang);
    }
    __syncthreads();

    int ddg = (t & 15) * 4;
    float4 qr[4];

    auto prefetch = [&](int st) {
        #pragma unroll
        for (int j = 0; j < 4; ++j) {
            int tok = (j * 256 + t) >> 4;
            qr[j] = ldcs4(&qb[(size_t)(st * SB2 + tok) * Esz + ddg]);
        }
    };
    auto commit = [&](int st, int buf) {
        __half* x = X + buf * XB2;
        #pragma unroll
        for (int j = 0; j < 4; ++j) {
            int tok = (j * 256 + t) >> 4;
            int gtok = st * SB2 + tok;
            float s = ssh[gtok], c = csh[gtok];
            float rq[4] = { fmaxf(qr[j].x, 0.f), fmaxf(qr[j].y, 0.f),
                            fmaxf(qr[j].z, 0.f), fmaxf(qr[j].w, 0.f) };
            float xs[4], xc[4], zpart = 0.f;
            #pragma unroll
            for (int i = 0; i < 4; ++i) {
                xs[i] = rq[i] * s; xc[i] = rq[i] * c;
                zpart += xs[i] * wsh[ddg + i] + xc[i] * wsh[64 + ddg + i];
            }
            *(uint2*)&x[tok * FS2 + ddg] =
                make_uint2(pk16(xs[0], xs[1]), pk16(xs[2], xs[3]));
            *(uint2*)&x[tok * FS2 + 64 + ddg] =
                make_uint2(pk16(xc[0], xc[1]), pk16(xc[2], xc[3]));
            #pragma unroll
            for (int o = 1; o < 16; o <<= 1)
                zpart += __shfl_xor_sync(0xffffffffu, zpart, o, 32);
            if ((t & 15) == 0) zsh[gtok] = 1.f / fmaxf(zpart, 1e-6f);
        }
    };

    int w = t >> 5, lane = t & 31;
    int gid = lane >> 2, tid = lane & 3;
    int tg = w >> 2;
    int mg = w & 3;
    int rn = lane & 15;
    int cn = ((lane >> 4) & 1) * 8;

    auto do_mma = [&](int st) {
        const __half* x = X + (st & 1) * XB2;
        float acc[2][2][4];
        #pragma unroll
        for (int i = 0; i < 2; ++i)
            #pragma unroll
            for (int j = 0; j < 2; ++j)
                #pragma unroll
                for (int q = 0; q < 4; ++q) acc[i][j][q] = 0.f;

        #pragma unroll
        for (int ko = 0; ko < 128; ko += 16) {
            u32 ah[2][4], bh[4];
            #pragma unroll
            for (int i = 0; i < 2; ++i)
                ldsm4(ah[i], sh_addr(&x[(tg * 32 + i * 16 + rn) * FS2 + ko + cn]));
            ldsm4(bh, sh_addr(&Kh[(mg * 16 + rn) * FS2 + ko + cn]));
            #pragma unroll
            for (int i = 0; i < 2; ++i) {
                mma_f16(acc[i][0], ah[i], bh[0], bh[2]);
                mma_f16(acc[i][1], ah[i], bh[1], bh[3]);
            }
        }

        float* ob = O + ((size_t)n * Lsz + l0 + st * SB2 + tg * 32) * 64;
        #pragma unroll
        for (int i = 0; i < 2; ++i) {
            int r1 = i * 16 + gid;
            int zb = st * SB2 + tg * 32 + r1;
            float z1 = zsh[zb], z2 = zsh[zb + 8];
            #pragma unroll
            for (int j = 0; j < 2; ++j) {
                int nb = mg * 16 + j * 8 + tid * 2;
                stcs2(&ob[(size_t)r1 * 64 + nb],
                      acc[i][j][0] * z1, acc[i][j][1] * z1);
                stcs2(&ob[(size_t)(r1 + 8) * 64 + nb],
                      acc[i][j][2] * z2, acc[i][j][3] * z2);
            }
        }
    };

    prefetch(0);
    commit(0, 0);
    asm volatile("cp.async.wait_group 0;" ::: "memory");
    __syncthreads();

    #pragma unroll
    for (int st = 0; st < NSUB; ++st) {
        if (st + 1 < NSUB) prefetch(st + 1);
        do_mma(st);
        if (st + 1 < NSUB) {
            commit(st + 1, (st + 1) & 1);
            __syncthreads();
        }
    }
}

// ---------------------------------------------------------------------------
extern "C" void kernel_launch(void* const* d_in, const int* in_sizes, int n_in,
                              void* d_out, int out_size) {
    const float* q = (const float*)d_in[0];
    const float* k = (const float*)d_in[1];
    const float* v = (const float*)d_in[2];
    const float* m = (const float*)d_in[3];
    float* out = (float*)d_out;

    cudaFuncSetAttribute(k_phase1, cudaFuncAttributeMaxDynamicSharedMemorySize,
                         SM1_BYTES);
    cudaFuncSetAttribute(k_phase2, cudaFuncAttributeMaxDynamicSharedMemorySize,
                         SM2_BYTES);

    k_phase1<<<HEADS * SPLIT, 256, SM1_BYTES>>>(k, v, m);
    k_phase2<<<HEADS * 32, 256, SM2_BYTES>>>(q, out);
}

// round 17
// speedup vs baseline: 1.1919x; 1.1919x over previous
#include <cuda_runtime.h>
#include <cuda_fp16.h>
#include <math.h>

#define Bsz   4
#define Lsz   4096
#define Esz   1024
#define HEADS 64
#define SPLIT 9
#define CHUNK 480            // chunks 0..7: 480 tokens; chunk 8: 256
#define KC    32
#define DEPTH 4

#define PART   8320
#define OFF_W  8192

typedef unsigned int u32;

__device__ float g_part[HEADS * SPLIT * PART];
__device__ __half g_kvt_h[HEADS * 8192];   // KV^T fp16 [head][m][f]
__device__ float g_w[HEADS * 128];

// ---- helpers ---------------------------------------------------------------
__device__ __forceinline__ void mma_f16(float* c, const u32* a, u32 b0, u32 b1) {
    asm("mma.sync.aligned.m16n8k16.row.col.f32.f16.f16.f32 "
        "{%0,%1,%2,%3}, {%4,%5,%6,%7}, {%8,%9}, {%0,%1,%2,%3};"
        : "+f"(c[0]), "+f"(c[1]), "+f"(c[2]), "+f"(c[3])
        : "r"(a[0]), "r"(a[1]), "r"(a[2]), "r"(a[3]), "r"(b0), "r"(b1));
}
__device__ __forceinline__ u32 sh_addr(const void* p) {
    return (u32)__cvta_generic_to_shared(p);
}
__device__ __forceinline__ void ldsm4(u32* r, u32 a) {
    asm volatile("ldmatrix.sync.aligned.m8n8.x4.shared.b16 {%0,%1,%2,%3}, [%4];"
        : "=r"(r[0]), "=r"(r[1]), "=r"(r[2]), "=r"(r[3]) : "r"(a));
}
__device__ __forceinline__ void ldsm4t(u32* r, u32 a) {
    asm volatile("ldmatrix.sync.aligned.m8n8.x4.trans.shared.b16 {%0,%1,%2,%3}, [%4];"
        : "=r"(r[0]), "=r"(r[1]), "=r"(r[2]), "=r"(r[3]) : "r"(a));
}
__device__ __forceinline__ u32 pk16(float a, float b) {
    u32 r;
    asm("cvt.rn.f16x2.f32 %0, %1, %2;" : "=r"(r) : "f"(b), "f"(a));
    return r;
}
__device__ __forceinline__ void cpa16(u32 saddr, const void* g) {
    asm volatile("cp.async.ca.shared.global [%0], [%1], 16;" :: "r"(saddr), "l"(g));
}
__device__ __forceinline__ float4 ldcs4(const float* p) {
    float4 r;
    asm volatile("ld.global.cs.v4.f32 {%0,%1,%2,%3}, [%4];"
        : "=f"(r.x), "=f"(r.y), "=f"(r.z), "=f"(r.w) : "l"(p));
    return r;
}
__device__ __forceinline__ void stcs2(float* p, float a, float b) {
    asm volatile("st.global.cs.v2.f32 [%0], {%1,%2};" :: "l"(p), "f"(a), "f"(b));
}
#define BARS(id) asm volatile("bar.sync %0, 256;"   :: "r"(id) : "memory")
#define BARA(id) asm volatile("bar.arrive %0, 256;" :: "r"(id) : "memory")

// ---------------------------------------------------------------------------
// Phase 1: warp-specialized (4 producer + 4 consumer warps), 4-deep ring,
// single-plane fp16 V. SPLIT=9 for wave balance at 2 blocks/SM.
// ---------------------------------------------------------------------------
#define XSTR 136
#define TSTR 72
#define ST_X (KC * XSTR)
#define ST_T (KC * TSTR)
#define SM1_BYTES ((DEPTH*ST_X + DEPTH*ST_T) * 2 + (CHUNK*3 + 1024) * 4)

__global__ __launch_bounds__(256, 2) void k_phase1(const float* __restrict__ K,
                                                   const float* __restrict__ V,
                                                   const float* __restrict__ M) {
    extern __shared__ char sm1[];
    __half* Xh = (__half*)sm1;
    __half* Th = Xh + DEPTH * ST_X;
    float* ssh = (float*)(Th + DEPTH * ST_T);
    float* csh = ssh + CHUNK;
    float* msh = csh + CHUNK;
    float* ksp = msh + CHUNK;

    int blk = blockIdx.x;
    int n  = blk / SPLIT;
    int sp = blk - n * SPLIT;
    int b = n >> 4, h = n & 15;
    int l0 = sp * CHUNK;
    int cnt = Lsz - l0; if (cnt > CHUNK) cnt = CHUNK;   // 480 or 256
    int ng = cnt / KC;

    const float* kb = K + ((size_t)b * Lsz + l0) * Esz + h * 64;
    const float* vb = V + ((size_t)b * Lsz + l0) * Esz + h * 64;
    const float* mb = M + (size_t)b * Lsz + l0;

    int t = threadIdx.x;
    for (int i = t; i < cnt; i += 256) {
        int l = l0 + i;
        float ang = 1.5707963267948966f * (float)(l + 1) / (float)Lsz;
        float m = mb[i];
        ssh[i] = sinf(ang) * m;
        csh[i] = cosf(ang) * m;
        msh[i] = m;
    }
    __syncthreads();

    float* p = g_part + (size_t)blk * PART;

    if (t < 128) {
        // ------------------ producer warps ------------------
        int ddg = (t & 15) * 4;
        int pr  = t >> 4;
        float ksr[4] = {0,0,0,0}, kcr[4] = {0,0,0,0};

        for (int g = 0; g < ng; ++g) {
            int bb = g & (DEPTH - 1);
            if (g >= DEPTH) BARS(5 + bb);
            __half* xh = Xh + bb * ST_X;
            __half* th = Th + bb * ST_T;
            #pragma unroll
            for (int jj = 0; jj < 4; ++jj) {
                int tok = jj * 8 + pr;
                int li = g * KC + tok;
                float4 k4 = ldcs4(&kb[(size_t)li * Esz + ddg]);
                float4 v4 = ldcs4(&vb[(size_t)li * Esz + ddg]);
                float s = ssh[li], c = csh[li], m = msh[li];
                float rk[4] = { fmaxf(k4.x, 0.f), fmaxf(k4.y, 0.f),
                                fmaxf(k4.z, 0.f), fmaxf(k4.w, 0.f) };
                float sk[4], ck[4], vm[4] = { v4.x*m, v4.y*m, v4.z*m, v4.w*m };
                #pragma unroll
                for (int i = 0; i < 4; ++i) {
                    sk[i] = rk[i] * s; ck[i] = rk[i] * c;
                    ksr[i] += sk[i];   kcr[i] += ck[i];
                }
                *(uint2*)&xh[tok * XSTR + ddg] =
                    make_uint2(pk16(sk[0], sk[1]), pk16(sk[2], sk[3]));
                *(uint2*)&xh[tok * XSTR + 64 + ddg] =
                    make_uint2(pk16(ck[0], ck[1]), pk16(ck[2], ck[3]));
                *(uint2*)&th[tok * TSTR + ddg] =
                    make_uint2(pk16(vm[0], vm[1]), pk16(vm[2], vm[3]));
            }
            __threadfence_block();
            BARA(1 + bb);
        }
        #pragma unroll
        for (int i = 0; i < 4; ++i) {
            ksp[pr * 128 + ddg + i]      = ksr[i];
            ksp[pr * 128 + 64 + ddg + i] = kcr[i];
        }
    } else {
        // ------------------ consumer warps ------------------
        int t2 = t - 128;
        int w = t2 >> 5, lane = t2 & 31;
        int gid = lane >> 2, tid = lane & 3;
        int rb = w * 32;
        int ra = (lane & 7) + ((lane >> 4) & 1) * 8;
        int ca = ((lane >> 3) & 1) * 8;

        float acc[2][8][4];
        #pragma unroll
        for (int i = 0; i < 2; ++i)
            #pragma unroll
            for (int j = 0; j < 8; ++j)
                #pragma unroll
                for (int q = 0; q < 4; ++q) acc[i][j][q] = 0.f;

        for (int g = 0; g < ng; ++g) {
            int bb = g & (DEPTH - 1);
            BARS(1 + bb);
            __half* xh = Xh + bb * ST_X;
            __half* th = Th + bb * ST_T;
            #pragma unroll
            for (int ko = 0; ko < KC; ko += 16) {
                u32 ah[2][4];
                #pragma unroll
                for (int i = 0; i < 2; ++i)
                    ldsm4t(ah[i], sh_addr(&xh[(ko + ra) * XSTR + rb + i * 16 + ca]));
                #pragma unroll
                for (int jp = 0; jp < 4; ++jp) {
                    u32 bh[4];
                    ldsm4t(bh, sh_addr(&th[(ko + ra) * TSTR + jp * 16 + ca]));
                    #pragma unroll
                    for (int i = 0; i < 2; ++i) {
                        mma_f16(acc[i][2 * jp],     ah[i], bh[0], bh[2]);
                        mma_f16(acc[i][2 * jp + 1], ah[i], bh[1], bh[3]);
                    }
                }
            }
            BARA(5 + bb);
        }
        #pragma unroll
        for (int i = 0; i < 2; ++i) {
            int r = rb + 16 * i + gid;
            #pragma unroll
            for (int j = 0; j < 8; ++j) {
                int nb = j * 8 + tid * 2;
                *(float2*)&p[r * 64 + nb]       = make_float2(acc[i][j][0], acc[i][j][1]);
                *(float2*)&p[(r + 8) * 64 + nb] = make_float2(acc[i][j][2], acc[i][j][3]);
            }
        }
    }
    __syncthreads();
    if (t < 128) {
        float s = 0.f;
        #pragma unroll
        for (int r = 0; r < 8; ++r) s += ksp[r * 128 + t];
        p[OFF_W + t] = s;
    }
}

// ---------------------------------------------------------------------------
// Reduce: sum SPLIT fp32 partials; emit KV^T fp16 + fp32 w.
// 512 blocks: 8 slices of 1040 elements per head (includes w tail).
// ---------------------------------------------------------------------------
__global__ __launch_bounds__(256) void k_reduce() {
    int blk = blockIdx.x;
    int n = blk >> 3;
    int sl = blk & 7;
    int t = threadIdx.x;
    for (int idx = sl * 1040 + t; idx < sl * 1040 + 1040; idx += 256) {
        float s = 0.f;
        #pragma unroll
        for (int sp = 0; sp < SPLIT; ++sp)
            s += g_part[(size_t)(n * SPLIT + sp) * PART + idx];
        if (idx < 8192) {
            int f = idx >> 6, m = idx & 63;
            g_kvt_h[(size_t)n * 8192 + m * 128 + f] = __float2half_rn(s);
        } else {
            g_w[n * 128 + (idx - OFF_W)] = s;
        }
    }
}

// ---------------------------------------------------------------------------
// Phase 2 (R15, proven ~41-43us): 128-token blocks = 2 substages of 64
// tokens, double-buffered X; Q(st+1) prefetched into regs before MMA(st);
// KV via cp.async. 8 warps as 2(tok)x4(m). 3 blocks/SM.
// ---------------------------------------------------------------------------
#define TT2  128
#define SB2  64
#define NSUB 2
#define FS2  136
#define XB2  (SB2 * FS2)
#define X2_OFF   0
#define KH_OFF   (2 * XB2 * 2)
#define FP_OFF   (KH_OFF + 64 * FS2 * 2)
#define SM2_BYTES (FP_OFF + (128 + TT2 * 3) * 4)

__global__ __launch_bounds__(256, 3) void k_phase2(const float* __restrict__ Q,
                                                   float* __restrict__ O) {
    extern __shared__ char sm2[];
    __half* X   = (__half*)(sm2 + X2_OFF);
    __half* Kh  = (__half*)(sm2 + KH_OFF);
    float* wsh = (float*)(sm2 + FP_OFF);
    float* zsh = wsh + 128;
    float* ssh = zsh + TT2;
    float* csh = ssh + TT2;

    int blk = blockIdx.x;
    int n = blk >> 5;
    int tile = blk & 31;
    int b = n >> 4, h = n & 15;
    int l0 = tile * TT2;

    const float* qb = Q + ((size_t)b * Lsz + l0) * Esz + h * 64;
    int t = threadIdx.x;

    for (int idx = t; idx < 1024; idx += 256) {
        int mr = idx >> 4, c = idx & 15;
        cpa16(sh_addr(&Kh[mr * FS2 + c * 8]),
              &g_kvt_h[(size_t)n * 8192 + mr * 128 + c * 8]);
    }
    asm volatile("cp.async.commit_group;" ::: "memory");

    if (t < 128) {
        wsh[t] = g_w[n * 128 + t];
        int l = l0 + t;
        float ang = 1.5707963267948966f * (float)(l + 1) / (float)Lsz;
        ssh[t] = sinf(ang);
        csh[t] = cosf(ang);
    }
    __syncthreads();

    int ddg = (t & 15) * 4;
    float4 qr[4];

    auto prefetch = [&](int st) {
        #pragma unroll
        for (int j = 0; j < 4; ++j) {
            int tok = (j * 256 + t) >> 4;
            qr[j] = ldcs4(&qb[(size_t)(st * SB2 + tok) * Esz + ddg]);
        }
    };
    auto commit = [&](int st, int buf) {
        __half* x = X + buf * XB2;
        #pragma unroll
        for (int j = 0; j < 4; ++j) {
            int tok = (j * 256 + t) >> 4;
            int gtok = st * SB2 + tok;
            float s = ssh[gtok], c = csh[gtok];
            float rq[4] = { fmaxf(qr[j].x, 0.f), fmaxf(qr[j].y, 0.f),
                            fmaxf(qr[j].z, 0.f), fmaxf(qr[j].w, 0.f) };
            float xs[4], xc[4], zpart = 0.f;
            #pragma unroll
            for (int i = 0; i < 4; ++i) {
                xs[i] = rq[i] * s; xc[i] = rq[i] * c;
                zpart += xs[i] * wsh[ddg + i] + xc[i] * wsh[64 + ddg + i];
            }
            *(uint2*)&x[tok * FS2 + ddg] =
                make_uint2(pk16(xs[0], xs[1]), pk16(xs[2], xs[3]));
            *(uint2*)&x[tok * FS2 + 64 + ddg] =
                make_uint2(pk16(xc[0], xc[1]), pk16(xc[2], xc[3]));
            #pragma unroll
            for (int o = 1; o < 16; o <<= 1)
                zpart += __shfl_xor_sync(0xffffffffu, zpart, o, 32);
            if ((t & 15) == 0) zsh[gtok] = 1.f / fmaxf(zpart, 1e-6f);
        }
    };

    int w = t >> 5, lane = t & 31;
    int gid = lane >> 2, tid = lane & 3;
    int tg = w >> 2;
    int mg = w & 3;
    int rn = lane & 15;
    int cn = ((lane >> 4) & 1) * 8;

    auto do_mma = [&](int st) {
        const __half* x = X + (st & 1) * XB2;
        float acc[2][2][4];
        #pragma unroll
        for (int i = 0; i < 2; ++i)
            #pragma unroll
            for (int j = 0; j < 2; ++j)
                #pragma unroll
                for (int q = 0; q < 4; ++q) acc[i][j][q] = 0.f;

        #pragma unroll
        for (int ko = 0; ko < 128; ko += 16) {
            u32 ah[2][4], bh[4];
            #pragma unroll
            for (int i = 0; i < 2; ++i)
                ldsm4(ah[i], sh_addr(&x[(tg * 32 + i * 16 + rn) * FS2 + ko + cn]));
            ldsm4(bh, sh_addr(&Kh[(mg * 16 + rn) * FS2 + ko + cn]));
            #pragma unroll
            for (int i = 0; i < 2; ++i) {
                mma_f16(acc[i][0], ah[i], bh[0], bh[2]);
                mma_f16(acc[i][1], ah[i], bh[1], bh[3]);
            }
        }

        float* ob = O + ((size_t)n * Lsz + l0 + st * SB2 + tg * 32) * 64;
        #pragma unroll
        for (int i = 0; i < 2; ++i) {
            int r1 = i * 16 + gid;
            int zb = st * SB2 + tg * 32 + r1;
            float z1 = zsh[zb], z2 = zsh[zb + 8];
            #pragma unroll
            for (int j = 0; j < 2; ++j) {
                int nb = mg * 16 + j * 8 + tid * 2;
                stcs2(&ob[(size_t)r1 * 64 + nb],
                      acc[i][j][0] * z1, acc[i][j][1] * z1);
                stcs2(&ob[(size_t)(r1 + 8) * 64 + nb],
                      acc[i][j][2] * z2, acc[i][j][3] * z2);
            }
        }
    };

    prefetch(0);
    commit(0, 0);
    asm volatile("cp.async.wait_group 0;" ::: "memory");
    __syncthreads();

    #pragma unroll
    for (int st = 0; st < NSUB; ++st) {
        if (st + 1 < NSUB) prefetch(st + 1);
        do_mma(st);
        if (st + 1 < NSUB) {
            commit(st + 1, (st + 1) & 1);
            __syncthreads();
        }
    }
}

// ---------------------------------------------------------------------------
extern "C" void kernel_launch(void* const* d_in, const int* in_sizes, int n_in,
                              void* d_out, int out_size) {
    const float* q = (const float*)d_in[0];
    const float* k = (const float*)d_in[1];
    const float* v = (const float*)d_in[2];
    const float* m = (const float*)d_in[3];
    float* out = (float*)d_out;

    cudaFuncSetAttribute(k_phase1, cudaFuncAttributeMaxDynamicSharedMemorySize,
                         SM1_BYTES);
    cudaFuncSetAttribute(k_phase2, cudaFuncAttributeMaxDynamicSharedMemorySize,
                         SM2_BYTES);

    k_phase1<<<HEADS * SPLIT, 256, SM1_BYTES>>>(k, v, m);
    k_reduce<<<HEADS * 8, 256>>>();
    k_phase2<<<HEADS * 32, 256, SM2_BYTES>>>(q, out);
}